// round 6
// baseline (speedup 1.0000x reference)
#include <cuda_runtime.h>
#include <cuda_bf16.h>
#include <math.h>

// Problem dimensions (fixed by the reference)
#define M_DIM 32768
#define D_DIM 128
#define H_DIM 1024
#define O_DIM 929
#define O_PAD 1024

// ---------------------------------------------------------------------------
// Scratch (allocation-guard-safe: __device__ globals, uninitialized -> bss)
// ---------------------------------------------------------------------------
__device__ float g_h1[(size_t)M_DIM * H_DIM];      // elu(x@W1+b1)
__device__ float g_h2[(size_t)M_DIM * H_DIM];      // sigmoid(h1@W2+b2)
__device__ float g_logits[(size_t)M_DIM * O_DIM];  // h2@W3+b3
__device__ float g_W3p[(size_t)H_DIM * O_PAD];     // W3 padded to 1024 cols

// ---------------------------------------------------------------------------
// Pad W3 [1024 x 929] -> [1024 x 1024] (zeros beyond col 929)
// ---------------------------------------------------------------------------
__global__ void pad_w3_kernel(const float* __restrict__ W3, float* __restrict__ W3p) {
    int idx = blockIdx.x * 256 + threadIdx.x;         // over 1024*1024
    int c = idx & (O_PAD - 1);
    int r = idx >> 10;
    W3p[idx] = (c < O_DIM) ? W3[r * O_DIM + c] : 0.0f;
}

// ---------------------------------------------------------------------------
// Tiled SGEMM: C[M x N] = act(A[M x K] @ B[K x N] + bias)
//   BM=128, BN=128, BK=16, 256 threads, 8x8 per thread, double-buffered smem
//   act: 0 = ELU, 1 = sigmoid, 2 = identity
//   Writes only columns < Nout, with row stride ldC.
// ---------------------------------------------------------------------------
#define BM 128
#define BN 128
#define BK 16

__global__ void __launch_bounds__(256, 2)
gemm_bias_act(const float* __restrict__ A, const float* __restrict__ B,
              const float* __restrict__ bias, float* __restrict__ C,
              int N, int K, int Nout, int ldC, int act)
{
    __shared__ __align__(16) float As[2][BK][BM];   // A^T tile
    __shared__ __align__(16) float Bs[2][BK][BN];

    const int tid = threadIdx.x;
    const int bx = blockIdx.x, by = blockIdx.y;

    const float* Ablk = A + (size_t)by * BM * K;
    const float* Bblk = B + (size_t)bx * BN;

    // Global-load mapping: 512 float4 per tile for A and for B; 2 each/thread
    const int f0 = tid * 2, f1 = tid * 2 + 1;
    const int arow0 = f0 >> 2, ac40 = f0 & 3;   // A: 4 float4 per row of 16
    const int arow1 = f1 >> 2, ac41 = f1 & 3;
    const int brow0 = f0 >> 5, bc40 = f0 & 31;  // B: 32 float4 per row of 128
    const int brow1 = f1 >> 5, bc41 = f1 & 31;

    // ---- load tile 0 ----
    {
        float4 a0 = *(const float4*)(Ablk + (size_t)arow0 * K + ac40 * 4);
        float4 a1 = *(const float4*)(Ablk + (size_t)arow1 * K + ac41 * 4);
        float4 b0 = *(const float4*)(Bblk + (size_t)brow0 * N + bc40 * 4);
        float4 b1 = *(const float4*)(Bblk + (size_t)brow1 * N + bc41 * 4);
        As[0][ac40 * 4 + 0][arow0] = a0.x;
        As[0][ac40 * 4 + 1][arow0] = a0.y;
        As[0][ac40 * 4 + 2][arow0] = a0.z;
        As[0][ac40 * 4 + 3][arow0] = a0.w;
        As[0][ac41 * 4 + 0][arow1] = a1.x;
        As[0][ac41 * 4 + 1][arow1] = a1.y;
        As[0][ac41 * 4 + 2][arow1] = a1.z;
        As[0][ac41 * 4 + 3][arow1] = a1.w;
        *(float4*)&Bs[0][brow0][bc40 * 4] = b0;
        *(float4*)&Bs[0][brow1][bc41 * 4] = b1;
    }
    __syncthreads();

    float acc[8][8];
    #pragma unroll
    for (int i = 0; i < 8; i++)
        #pragma unroll
        for (int j = 0; j < 8; j++) acc[i][j] = 0.0f;

    const int tr = (tid >> 4) * 8;   // 0..120
    const int tc = (tid & 15) * 8;   // 0..120

    const int numT = K / BK;
    for (int t = 0; t < numT; t++) {
        const int cur = t & 1;
        float4 pa0, pa1, pb0, pb1;
        const bool pf = (t + 1 < numT);
        if (pf) {
            const int k0 = (t + 1) * BK;
            pa0 = *(const float4*)(Ablk + (size_t)arow0 * K + k0 + ac40 * 4);
            pa1 = *(const float4*)(Ablk + (size_t)arow1 * K + k0 + ac41 * 4);
            pb0 = *(const float4*)(Bblk + (size_t)(k0 + brow0) * N + bc40 * 4);
            pb1 = *(const float4*)(Bblk + (size_t)(k0 + brow1) * N + bc41 * 4);
        }

        #pragma unroll
        for (int k = 0; k < BK; k++) {
            float4 x0 = *(const float4*)&As[cur][k][tr];
            float4 x1 = *(const float4*)&As[cur][k][tr + 4];
            float4 y0 = *(const float4*)&Bs[cur][k][tc];
            float4 y1 = *(const float4*)&Bs[cur][k][tc + 4];
            float av[8] = {x0.x, x0.y, x0.z, x0.w, x1.x, x1.y, x1.z, x1.w};
            float bv[8] = {y0.x, y0.y, y0.z, y0.w, y1.x, y1.y, y1.z, y1.w};
            #pragma unroll
            for (int i = 0; i < 8; i++)
                #pragma unroll
                for (int j = 0; j < 8; j++)
                    acc[i][j] = fmaf(av[i], bv[j], acc[i][j]);
        }

        if (pf) {
            const int nb = cur ^ 1;
            As[nb][ac40 * 4 + 0][arow0] = pa0.x;
            As[nb][ac40 * 4 + 1][arow0] = pa0.y;
            As[nb][ac40 * 4 + 2][arow0] = pa0.z;
            As[nb][ac40 * 4 + 3][arow0] = pa0.w;
            As[nb][ac41 * 4 + 0][arow1] = pa1.x;
            As[nb][ac41 * 4 + 1][arow1] = pa1.y;
            As[nb][ac41 * 4 + 2][arow1] = pa1.z;
            As[nb][ac41 * 4 + 3][arow1] = pa1.w;
            *(float4*)&Bs[nb][brow0][bc40 * 4] = pb0;
            *(float4*)&Bs[nb][brow1][bc41 * 4] = pb1;
            __syncthreads();
        }
    }

    // ---- epilogue: bias + activation + guarded store ----
    const int grow = by * BM + tr;
    const int gcol = bx * BN + tc;
    #pragma unroll
    for (int i = 0; i < 8; i++) {
        #pragma unroll
        for (int j = 0; j < 8; j++) {
            const int gc = gcol + j;
            if (gc < Nout) {
                float v = acc[i][j] + bias[gc];
                if (act == 0) v = (v > 0.0f) ? v : expm1f(v);         // ELU
                else if (act == 1) v = 1.0f / (1.0f + expf(-v));       // sigmoid
                C[(size_t)(grow + i) * ldC + gc] = v;
            }
        }
    }
}

// ---------------------------------------------------------------------------
// Gumbel-softmax epilogue. One warp per row; segment y-values kept in regs.
// VAR_NUM = [29,2,1,6,7,59,1,24,76,711,3,9,1]  (offsets precomputed)
// n==1 segments pass logits through unchanged.
// ---------------------------------------------------------------------------
__global__ void __launch_bounds__(256)
gumbel_softmax_kernel(const float* __restrict__ logits,
                      const float* __restrict__ u,
                      float* __restrict__ out)
{
    const int warp = threadIdx.x >> 5;
    const int lane = threadIdx.x & 31;
    const int row = blockIdx.x * 8 + warp;

    const float* lr = logits + (size_t)row * O_DIM;
    const float* ur = u + (size_t)row * O_DIM;
    float* orow = out + (size_t)row * O_DIM;

    const int offs[13] = {0, 29, 31, 32, 38, 45, 104, 105, 129, 205, 916, 919, 928};
    const int nums[13] = {29, 2, 1, 6, 7, 59, 1, 24, 76, 711, 3, 9, 1};
    const float invT = 1.0f / 0.8f;
    const float EPS = 1e-20f;

    for (int s = 0; s < 13; s++) {
        const int o = offs[s];
        const int n = nums[s];
        if (n == 1) {
            if (lane == 0) orow[o] = lr[o];
            continue;
        }
        float yv[23];                 // ceil(711/32) = 23 covers the widest segment
        float mx = -1e30f;
        #pragma unroll
        for (int it = 0; it < 23; it++) {
            const int i = lane + it * 32;
            float y = -1e30f;
            if (i < n) {
                const float g = -logf(-logf(ur[o + i] + EPS) + EPS);
                y = (lr[o + i] + g) * invT;
            }
            yv[it] = y;
            mx = fmaxf(mx, y);
        }
        #pragma unroll
        for (int d = 16; d; d >>= 1) mx = fmaxf(mx, __shfl_xor_sync(0xFFFFFFFFu, mx, d));

        float sum = 0.0f;
        #pragma unroll
        for (int it = 0; it < 23; it++) {
            const int i = lane + it * 32;
            float e = 0.0f;
            if (i < n) e = expf(yv[it] - mx);
            yv[it] = e;
            sum += e;
        }
        #pragma unroll
        for (int d = 16; d; d >>= 1) sum += __shfl_xor_sync(0xFFFFFFFFu, sum, d);
        const float inv = 1.0f / sum;

        #pragma unroll
        for (int it = 0; it < 23; it++) {
            const int i = lane + it * 32;
            if (i < n) orow[o + i] = yv[it] * inv;
        }
    }
}

// ---------------------------------------------------------------------------
// kernel_launch: pad W3, 3 GEMMs (fused bias+act), gumbel-softmax.
// Graph-capturable: kernel launches only, no sync, no alloc.
// ---------------------------------------------------------------------------
extern "C" void kernel_launch(void* const* d_in, const int* in_sizes, int n_in,
                              void* d_out, int out_size)
{
    const float* x  = (const float*)d_in[0];
    const float* W1 = (const float*)d_in[1];
    const float* b1 = (const float*)d_in[2];
    const float* W2 = (const float*)d_in[3];
    const float* b2 = (const float*)d_in[4];
    const float* W3 = (const float*)d_in[5];
    const float* b3 = (const float*)d_in[6];
    const float* u  = (const float*)d_in[7];
    float* out = (float*)d_out;

    float *h1p, *h2p, *lgp, *w3p;
    cudaGetSymbolAddress((void**)&h1p, g_h1);
    cudaGetSymbolAddress((void**)&h2p, g_h2);
    cudaGetSymbolAddress((void**)&lgp, g_logits);
    cudaGetSymbolAddress((void**)&w3p, g_W3p);

    // Pad W3 to 1024 columns (float4 alignment for the GEMM)
    pad_w3_kernel<<<(H_DIM * O_PAD) / 256, 256>>>(W3, w3p);

    dim3 grid(H_DIM / BN, M_DIM / BM);   // (8, 256)
    // Layer 1: h1 = elu(x @ W1 + b1), K = 128
    gemm_bias_act<<<grid, 256>>>(x, W1, b1, h1p, H_DIM, D_DIM, H_DIM, H_DIM, 0);
    // Layer 2: h2 = sigmoid(h1 @ W2 + b2), K = 1024
    gemm_bias_act<<<grid, 256>>>(h1p, W2, b2, h2p, H_DIM, H_DIM, H_DIM, H_DIM, 1);
    // Layer 3: logits = h2 @ W3p + b3 (write only cols < 929, ldC = 929)
    gemm_bias_act<<<grid, 256>>>(h2p, w3p, b3, lgp, O_PAD, H_DIM, O_DIM, O_DIM, 2);
    // Gumbel softmax per segment
    gumbel_softmax_kernel<<<M_DIM / 8, 256>>>(lgp, u, out);
}

// round 11
// speedup vs baseline: 2.4495x; 2.4495x over previous
#include <cuda_runtime.h>
#include <cuda_bf16.h>
#include <math.h>
#include <stdint.h>

// Problem dimensions (fixed by the reference)
#define M_DIM 32768
#define D_DIM 128
#define H_DIM 1024
#define O_DIM 929
#define LG_PITCH 1024   // padded logits pitch (float4-aligned rows)

#if defined(__CUDA_ARCH_FEAT_SM103_ALL) || defined(__CUDA_ARCH_FEAT_SM100_ALL)
#define HAS_TCGEN05 1
#endif

// ---------------------------------------------------------------------------
// Scratch (__device__ globals — allocation-guard-safe)
// ---------------------------------------------------------------------------
__device__ __align__(256) __nv_bfloat16 g_xhi[(size_t)M_DIM * D_DIM];
__device__ __align__(256) __nv_bfloat16 g_xlo[(size_t)M_DIM * D_DIM];
__device__ __align__(256) __nv_bfloat16 g_a1hi[(size_t)M_DIM * H_DIM];
__device__ __align__(256) __nv_bfloat16 g_a1lo[(size_t)M_DIM * H_DIM];
__device__ __align__(256) __nv_bfloat16 g_a2hi[(size_t)M_DIM * H_DIM];
__device__ __align__(256) __nv_bfloat16 g_a2lo[(size_t)M_DIM * H_DIM];
__device__ __align__(256) float         g_logits[(size_t)M_DIM * LG_PITCH];
__device__ __align__(256) __nv_bfloat16 g_w1hi[(size_t)H_DIM * D_DIM];
__device__ __align__(256) __nv_bfloat16 g_w1lo[(size_t)H_DIM * D_DIM];
__device__ __align__(256) __nv_bfloat16 g_w2hi[(size_t)H_DIM * H_DIM];
__device__ __align__(256) __nv_bfloat16 g_w2lo[(size_t)H_DIM * H_DIM];
__device__ __align__(256) __nv_bfloat16 g_w3hi[(size_t)H_DIM * H_DIM];
__device__ __align__(256) __nv_bfloat16 g_w3lo[(size_t)H_DIM * H_DIM];

// ---------------------------------------------------------------------------
// Common PTX helpers (baseline ISA — legal on plain sm_103)
// ---------------------------------------------------------------------------
__device__ __forceinline__ uint32_t smem_u32(const void* p) {
    uint32_t a;
    asm("{ .reg .u64 t; cvta.to.shared.u64 t, %1; cvt.u32.u64 %0, t; }" : "=r"(a) : "l"(p));
    return a;
}
#define SW128(o) ((o) ^ (((o) >> 3) & 0x70))

#define CP_ASYNC16(dst, src) \
    asm volatile("cp.async.cg.shared.global [%0], [%1], 16;" :: "r"(dst), "l"(src) : "memory")
#define CP_COMMIT() asm volatile("cp.async.commit_group;" ::: "memory")
#define CP_WAIT(n)  asm volatile("cp.async.wait_group %0;" :: "n"(n) : "memory")

#define LDSM_X4(r0, r1, r2, r3, addr) \
    asm volatile("ldmatrix.sync.aligned.m8n8.x4.shared.b16 {%0,%1,%2,%3}, [%4];" \
                 : "=r"(r0), "=r"(r1), "=r"(r2), "=r"(r3) : "r"(addr))

#define MMA16816(d, a, b0, b1) \
    asm volatile("mma.sync.aligned.m16n8k16.row.col.f32.bf16.bf16.f32 " \
                 "{%0,%1,%2,%3}, {%4,%5,%6,%7}, {%8,%9}, {%0,%1,%2,%3};" \
                 : "+f"((d)[0]), "+f"((d)[1]), "+f"((d)[2]), "+f"((d)[3]) \
                 : "r"((a)[0]), "r"((a)[1]), "r"((a)[2]), "r"((a)[3]), "r"(b0), "r"(b1))

// ---------------------------------------------------------------------------
// Prep kernels
// ---------------------------------------------------------------------------
__global__ void split_x_kernel(const float* __restrict__ x,
                               __nv_bfloat16* __restrict__ hi,
                               __nv_bfloat16* __restrict__ lo, int n) {
    int i = blockIdx.x * 256 + threadIdx.x;
    if (i < n) {
        float v = x[i];
        __nv_bfloat16 h = __float2bfloat16(v);
        hi[i] = h;
        lo[i] = __float2bfloat16(v - __bfloat162float(h));
    }
}

// W [K, Nsrc] row-major  ->  Bt [Npad, K] with Bt[n][k] = (n < Nsrc) ? W[k][n] : 0
__global__ void wsplit_kernel(const float* __restrict__ W,
                              __nv_bfloat16* __restrict__ hi,
                              __nv_bfloat16* __restrict__ lo,
                              int K, int Nsrc, int Npad) {
    int idx = blockIdx.x * 256 + threadIdx.x;
    int n = idx / K, k = idx - n * K;
    float v = (n < Nsrc) ? W[(size_t)k * Nsrc + n] : 0.0f;
    __nv_bfloat16 h = __float2bfloat16(v);
    hi[idx] = h;
    lo[idx] = __float2bfloat16(v - __bfloat162float(h));
}

// ===========================================================================
// PATH A: mma.sync (baseline PTX, runs when compiled for plain sm_103)
//   C[128x128 tile] = act( A@B^T over 3 split-passes + bias )
//   8 warps: 2(m) x 4(n), warp tile 64x32, m16n8k16 frags, K-chunk 64.
// ===========================================================================
#define MM_ABUF(b) ((uint32_t)(b) * 32768u)
#define MM_BBUF(b) ((uint32_t)(b) * 32768u + 16384u)
#define MM_SMEM 65536

__device__ __forceinline__ void mm_load_stage(
    int s, int buf, int tid, uint32_t sb, int K, int cpp,
    const __nv_bfloat16* Ahi, const __nv_bfloat16* Alo,
    const __nv_bfloat16* Bhi, const __nv_bfloat16* Blo,
    int rowBase, int colBase)
{
    int p = s / cpp;
    int kk = (s - p * cpp) << 6;
    const __nv_bfloat16* A = (p == 1) ? Alo : Ahi;
    const __nv_bfloat16* B = (p == 2) ? Blo : Bhi;
    const __nv_bfloat16* Ab = A + (size_t)rowBase * K + kk;
    const __nv_bfloat16* Bb = B + (size_t)colBase * K + kk;
    uint32_t sA = sb + MM_ABUF(buf), sB = sb + MM_BBUF(buf);
    #pragma unroll
    for (int i = 0; i < 8; i++) {
        int c = i * 256 + tid;
        int local = c & 1023;                 // 1024 float4 per operand tile
        int row = local >> 3, c16 = local & 7;
        uint32_t off = SW128((uint32_t)(row * 128 + c16 * 16));
        if (i < 4) CP_ASYNC16(sA + off, (const void*)(Ab + (size_t)row * K + c16 * 8));
        else       CP_ASYNC16(sB + off, (const void*)(Bb + (size_t)row * K + c16 * 8));
    }
    CP_COMMIT();
}

__global__ void __launch_bounds__(256, 2)
gemm_mma(const __nv_bfloat16* __restrict__ Ahi, const __nv_bfloat16* __restrict__ Alo,
         const __nv_bfloat16* __restrict__ Bhi, const __nv_bfloat16* __restrict__ Blo,
         const float* __restrict__ bias, int K, int act,
         float* __restrict__ outF,
         __nv_bfloat16* __restrict__ outHi, __nv_bfloat16* __restrict__ outLo)
{
#ifndef HAS_TCGEN05
    extern __shared__ __align__(1024) char smem[];
    uint32_t sb = smem_u32(smem);
    const int tid = threadIdx.x;
    const int lane = tid & 31, w = tid >> 5;
    const int wm = w & 1, wn = w >> 1;            // 2 x 4 warp grid
    const int rowBase = blockIdx.y * 128, colBase = blockIdx.x * 128;
    const int cpp = K >> 6;
    const int S = 3 * cpp;

    float acc[4][4][4];
    #pragma unroll
    for (int i = 0; i < 4; i++)
        #pragma unroll
        for (int j = 0; j < 4; j++)
            #pragma unroll
            for (int q = 0; q < 4; q++) acc[i][j][q] = 0.0f;

    mm_load_stage(0, 0, tid, sb, K, cpp, Ahi, Alo, Bhi, Blo, rowBase, colBase);

    const int lrow = lane & 15;
    const int lcol = (lane >> 4) * 16;

    for (int s = 0; s < S; s++) {
        const int cur = s & 1;
        if (s + 1 < S) {
            mm_load_stage(s + 1, cur ^ 1, tid, sb, K, cpp, Ahi, Alo, Bhi, Blo, rowBase, colBase);
            CP_WAIT(1);
        } else {
            CP_WAIT(0);
        }
        __syncthreads();

        const uint32_t sA = sb + MM_ABUF(cur), sB = sb + MM_BBUF(cur);
        #pragma unroll
        for (int ks = 0; ks < 4; ks++) {
            const int colb = ks * 32 + lcol;
            uint32_t a[4][4], b[4][2];
            #pragma unroll
            for (int mf = 0; mf < 4; mf++) {
                int r = wm * 64 + mf * 16 + lrow;
                LDSM_X4(a[mf][0], a[mf][1], a[mf][2], a[mf][3],
                        sA + SW128((uint32_t)(r * 128 + colb)));
            }
            #pragma unroll
            for (int np = 0; np < 2; np++) {
                int r = wn * 32 + np * 16 + lrow;
                uint32_t t0, t1, t2, t3;
                LDSM_X4(t0, t1, t2, t3, sB + SW128((uint32_t)(r * 128 + colb)));
                b[np * 2 + 0][0] = t0; b[np * 2 + 0][1] = t2;
                b[np * 2 + 1][0] = t1; b[np * 2 + 1][1] = t3;
            }
            #pragma unroll
            for (int mf = 0; mf < 4; mf++)
                #pragma unroll
                for (int nf = 0; nf < 4; nf++)
                    MMA16816(acc[mf][nf], a[mf], b[nf][0], b[nf][1]);
        }
        __syncthreads();
    }

    // ---- epilogue ----
    const int qr = lane >> 2, qc = (lane & 3) * 2;
    #pragma unroll
    for (int mf = 0; mf < 4; mf++) {
        #pragma unroll
        for (int nf = 0; nf < 4; nf++) {
            const int row0 = rowBase + wm * 64 + mf * 16 + qr;
            const int c = colBase + wn * 32 + nf * 8 + qc;
            const float bz0 = bias[c], bz1 = bias[c + 1];
            #pragma unroll
            for (int h = 0; h < 2; h++) {           // h=0: row, h=1: row+8
                const int row = row0 + h * 8;
                float v0 = acc[mf][nf][h * 2 + 0] + bz0;
                float v1 = acc[mf][nf][h * 2 + 1] + bz1;
                if (act == 2) {
                    float* orow = outF + (size_t)row * LG_PITCH;
                    if (c + 1 < O_DIM) { *(float2*)&orow[c] = make_float2(v0, v1); }
                    else if (c < O_DIM) { orow[c] = v0; }
                } else {
                    if (act == 0) {
                        v0 = (v0 > 0.0f) ? v0 : expm1f(v0);
                        v1 = (v1 > 0.0f) ? v1 : expm1f(v1);
                    } else {
                        v0 = 1.0f / (1.0f + __expf(-v0));
                        v1 = 1.0f / (1.0f + __expf(-v1));
                    }
                    __nv_bfloat16 h0 = __float2bfloat16(v0), h1 = __float2bfloat16(v1);
                    __nv_bfloat16 l0 = __float2bfloat16(v0 - __bfloat162float(h0));
                    __nv_bfloat16 l1 = __float2bfloat16(v1 - __bfloat162float(h1));
                    __nv_bfloat162 hh = __nv_bfloat162(h0, h1);
                    __nv_bfloat162 ll = __nv_bfloat162(l0, l1);
                    *(uint32_t*)(outHi + (size_t)row * H_DIM + c) = *(uint32_t*)&hh;
                    *(uint32_t*)(outLo + (size_t)row * H_DIM + c) = *(uint32_t*)&ll;
                }
            }
        }
    }
#endif  // !HAS_TCGEN05
}

// ===========================================================================
// PATH B: tcgen05 (compiled only under an 'a'/feature target; else empty)
// ===========================================================================
#define ABUF(b) (1024u + (uint32_t)(b) * 32768u)
#define BBUF(b) (66560u + (uint32_t)(b) * 32768u)
#define SMEM_BYTES 132096

#ifdef HAS_TCGEN05
#define TC_ALLOC(smem_addr, n) \
    asm volatile("tcgen05.alloc.cta_group::1.sync.aligned.shared::cta.b32 [%0], %1;" \
                 :: "r"(smem_addr), "r"((uint32_t)(n)) : "memory")
#define TC_RELINQ() asm volatile("tcgen05.relinquish_alloc_permit.cta_group::1.sync.aligned;")
#define TC_DEALLOC(t, n) \
    asm volatile("tcgen05.dealloc.cta_group::1.sync.aligned.b32 %0, %1;" :: "r"(t), "r"((uint32_t)(n)))
#define TC_COMMIT(mbar) \
    asm volatile("tcgen05.commit.cta_group::1.mbarrier::arrive::one.shared::cluster.b64 [%0];" \
                 :: "r"(mbar) : "memory")
#define TC_FENCE_AFTER()  asm volatile("tcgen05.fence::after_thread_sync;" ::: "memory")
#define TC_FENCE_BEFORE() asm volatile("tcgen05.fence::before_thread_sync;" ::: "memory")
#define TC_WAIT_LD() asm volatile("tcgen05.wait::ld.sync.aligned;" ::: "memory")
#define MBAR_INIT(a, c) \
    asm volatile("mbarrier.init.shared.b64 [%0], %1;" :: "r"(a), "r"((uint32_t)(c)) : "memory")
#define MBAR_WAIT(a, ph) do {                                                         \
    uint32_t _m = (a), _p = (uint32_t)(ph), _d;                                       \
    asm volatile("{ .reg .pred p; mbarrier.try_wait.parity.acquire.cta.shared::cta.b64 p, [%1], %2; selp.b32 %0, 1, 0, p; }" \
                 : "=r"(_d) : "r"(_m), "r"(_p) : "memory");                           \
    if (!_d) {                                                                        \
        asm volatile("{ .reg .pred P1; WL_%=:\n\t"                                    \
                     "mbarrier.try_wait.parity.acquire.cta.shared::cta.b64 P1, [%0], %1, 0x989680;\n\t" \
                     "@P1 bra.uni WD_%=;\n\t bra.uni WL_%=;\n\t WD_%=: }"             \
                     :: "r"(_m), "r"(_p) : "memory");                                 \
    }                                                                                 \
} while (0)

__device__ __forceinline__ uint32_t elect1() {
    uint32_t p;
    asm volatile("{ .reg .pred p; elect.sync _|p, 0xFFFFFFFF; selp.b32 %0, 1, 0, p; }" : "=r"(p));
    return p;
}
__device__ __forceinline__ uint64_t mkdesc(uint32_t addr) {
    return (2ULL << 61) | (1ULL << 46) | (64ULL << 32) | (1ULL << 16) |
           ((uint64_t)(addr >> 4) & 0x3FFF);
}
#define IDESC 0x8200490u
__device__ __forceinline__ void mma_f16_ss(uint32_t d, uint64_t a, uint64_t b, uint32_t acc) {
    asm volatile(
        "{\n\t.reg .pred p;\n\tsetp.ne.u32 p, %5, 0;\n\t"
        "tcgen05.mma.cta_group::1.kind::f16 [%0], %1, %2, %3, {%4, %4, %4, %4}, p;\n\t}"
        :: "r"(d), "l"(a), "l"(b), "r"(IDESC), "r"(0u), "r"(acc) : "memory");
}
__device__ __forceinline__ void ldtm_x32(uint32_t* r, uint32_t addr) {
    asm volatile(
        "tcgen05.ld.sync.aligned.32x32b.x32.b32 "
        "{%0, %1, %2, %3, %4, %5, %6, %7, "
        " %8, %9, %10, %11, %12, %13, %14, %15, "
        " %16, %17, %18, %19, %20, %21, %22, %23, "
        " %24, %25, %26, %27, %28, %29, %30, %31}, [%32];"
        : "=r"(r[0]),  "=r"(r[1]),  "=r"(r[2]),  "=r"(r[3]),
          "=r"(r[4]),  "=r"(r[5]),  "=r"(r[6]),  "=r"(r[7]),
          "=r"(r[8]),  "=r"(r[9]),  "=r"(r[10]), "=r"(r[11]),
          "=r"(r[12]), "=r"(r[13]), "=r"(r[14]), "=r"(r[15]),
          "=r"(r[16]), "=r"(r[17]), "=r"(r[18]), "=r"(r[19]),
          "=r"(r[20]), "=r"(r[21]), "=r"(r[22]), "=r"(r[23]),
          "=r"(r[24]), "=r"(r[25]), "=r"(r[26]), "=r"(r[27]),
          "=r"(r[28]), "=r"(r[29]), "=r"(r[30]), "=r"(r[31])
        : "r"(addr));
}

__device__ __forceinline__ void tc_load_stage(
    int s, int buf, int tid, uint32_t sb, int K, int cpp,
    const __nv_bfloat16* Ahi, const __nv_bfloat16* Alo,
    const __nv_bfloat16* Bhi, const __nv_bfloat16* Blo,
    int rowBase, int colBase)
{
    int p = s / cpp;
    int kk = (s - p * cpp) << 6;
    const __nv_bfloat16* A = (p == 1) ? Alo : Ahi;
    const __nv_bfloat16* B = (p == 2) ? Blo : Bhi;
    const __nv_bfloat16* Abase = A + (size_t)rowBase * K + kk;
    const __nv_bfloat16* Bbase = B + (size_t)colBase * K + kk;
    uint32_t sA = sb + ABUF(buf), sB = sb + BBUF(buf);
    #pragma unroll
    for (int i = 0; i < 16; i++) {
        int c = i * 256 + tid;
        int local = c & 2047;
        int row = local >> 3, c16 = local & 7;
        uint32_t off = SW128((uint32_t)(row * 128 + c16 * 16));
        if (i < 8) CP_ASYNC16(sA + off, (const void*)(Abase + (size_t)row * K + c16 * 8));
        else       CP_ASYNC16(sB + off, (const void*)(Bbase + (size_t)row * K + c16 * 8));
    }
    CP_COMMIT();
}
#endif  // HAS_TCGEN05

__global__ void __launch_bounds__(256, 1)
gemm_tc(const __nv_bfloat16* __restrict__ Ahi, const __nv_bfloat16* __restrict__ Alo,
        const __nv_bfloat16* __restrict__ Bhi, const __nv_bfloat16* __restrict__ Blo,
        const float* __restrict__ bias, int K, int act,
        float* __restrict__ outF,
        __nv_bfloat16* __restrict__ outHi, __nv_bfloat16* __restrict__ outLo)
{
#ifdef HAS_TCGEN05
    extern __shared__ __align__(1024) char smem[];
    uint32_t sb = smem_u32(smem);
    const int tid = threadIdx.x;
    const int rowBase = blockIdx.y * 256, colBase = blockIdx.x * 256;
    const int cpp = K >> 6;
    const int S = 3 * cpp;

    if (tid < 32) TC_ALLOC(sb, 512);
    if (tid == 0) { MBAR_INIT(sb + 8, 1); MBAR_INIT(sb + 16, 1); }
    __syncthreads();
    uint32_t tmem;
    asm volatile("ld.shared.b32 %0, [%1];" : "=r"(tmem) : "r"(sb));
    if (tid < 32) TC_RELINQ();

    tc_load_stage(0, 0, tid, sb, K, cpp, Ahi, Alo, Bhi, Blo, rowBase, colBase);

    int ph0 = 0, ph1 = 0;
    for (int s = 0; s < S; s++) {
        const int cur = s & 1;
        if (s + 1 < S) {
            const int nb = cur ^ 1;
            if (s >= 1) {
                if (nb == 0) { MBAR_WAIT(sb + 8, ph0);  ph0 ^= 1; }
                else         { MBAR_WAIT(sb + 16, ph1); ph1 ^= 1; }
            }
            tc_load_stage(s + 1, nb, tid, sb, K, cpp, Ahi, Alo, Bhi, Blo, rowBase, colBase);
            CP_WAIT(1);
        } else {
            CP_WAIT(0);
        }
        __syncthreads();

        if (tid < 32 && elect1()) {
            asm volatile("fence.proxy.async;" ::: "memory");
            const uint32_t aA = sb + ABUF(cur), aB = sb + BBUF(cur);
            const uint64_t dA0 = mkdesc(aA), dA1 = mkdesc(aA + 16384);
            const uint64_t dB0 = mkdesc(aB), dB1 = mkdesc(aB + 16384);
            const uint32_t af = (s > 0) ? 1u : 0u;
            #pragma unroll
            for (int k = 0; k < 4; k++) {
                const uint32_t acc = (k > 0) ? 1u : af;
                mma_f16_ss(tmem + 0,   dA0 + k * 2, dB0 + k * 2, acc);
                mma_f16_ss(tmem + 128, dA0 + k * 2, dB1 + k * 2, acc);
                mma_f16_ss(tmem + 256, dA1 + k * 2, dB0 + k * 2, acc);
                mma_f16_ss(tmem + 384, dA1 + k * 2, dB1 + k * 2, acc);
            }
            TC_COMMIT(sb + (cur ? 16u : 8u));
        }
    }

    MBAR_WAIT(sb + 8, ph0);
    MBAR_WAIT(sb + 16, ph1);
    TC_FENCE_AFTER();

    const int wg = tid >> 7;
    const int sp = (tid >> 5) & 3;
    const int lane = tid & 31;
    const int row = rowBase + wg * 128 + sp * 32 + lane;

    #pragma unroll 1
    for (int cb = 0; cb < 8; cb++) {
        uint32_t r[32];
        ldtm_x32(r, tmem + (uint32_t)(wg * 256 + cb * 32));
        TC_WAIT_LD();
        const int col0 = colBase + cb * 32;

        if (act == 2) {
            float* orow = outF + (size_t)row * LG_PITCH;
            #pragma unroll
            for (int i = 0; i < 32; i += 4) {
                const int c = col0 + i;
                if (c + 3 < O_DIM) {
                    float4 v;
                    v.x = __uint_as_float(r[i + 0]) + bias[c + 0];
                    v.y = __uint_as_float(r[i + 1]) + bias[c + 1];
                    v.z = __uint_as_float(r[i + 2]) + bias[c + 2];
                    v.w = __uint_as_float(r[i + 3]) + bias[c + 3];
                    *(float4*)&orow[c] = v;
                } else {
                    #pragma unroll
                    for (int j = 0; j < 4; j++)
                        if (c + j < O_DIM)
                            orow[c + j] = __uint_as_float(r[i + j]) + bias[c + j];
                }
            }
        } else {
            uint32_t hp[16], lp[16];
            #pragma unroll
            for (int i = 0; i < 32; i += 2) {
                float v0 = __uint_as_float(r[i + 0]) + bias[col0 + i + 0];
                float v1 = __uint_as_float(r[i + 1]) + bias[col0 + i + 1];
                if (act == 0) {
                    v0 = (v0 > 0.0f) ? v0 : expm1f(v0);
                    v1 = (v1 > 0.0f) ? v1 : expm1f(v1);
                } else {
                    v0 = 1.0f / (1.0f + __expf(-v0));
                    v1 = 1.0f / (1.0f + __expf(-v1));
                }
                __nv_bfloat16 h0 = __float2bfloat16(v0), h1 = __float2bfloat16(v1);
                __nv_bfloat16 l0 = __float2bfloat16(v0 - __bfloat162float(h0));
                __nv_bfloat16 l1 = __float2bfloat16(v1 - __bfloat162float(h1));
                __nv_bfloat162 h2 = __nv_bfloat162(h0, h1);
                __nv_bfloat162 l2 = __nv_bfloat162(l0, l1);
                hp[i >> 1] = *(uint32_t*)&h2;
                lp[i >> 1] = *(uint32_t*)&l2;
            }
            uint4* dH = (uint4*)(outHi + (size_t)row * H_DIM + col0);
            uint4* dL = (uint4*)(outLo + (size_t)row * H_DIM + col0);
            #pragma unroll
            for (int j = 0; j < 4; j++) {
                dH[j] = make_uint4(hp[4*j], hp[4*j+1], hp[4*j+2], hp[4*j+3]);
                dL[j] = make_uint4(lp[4*j], lp[4*j+1], lp[4*j+2], lp[4*j+3]);
            }
        }
    }
    TC_FENCE_BEFORE();
    __syncthreads();
    if (tid < 32) TC_DEALLOC(tmem, 512);
#endif  // HAS_TCGEN05
}

// ---------------------------------------------------------------------------
// Gumbel-softmax epilogue (warp per row, y in registers)
// ---------------------------------------------------------------------------
__global__ void __launch_bounds__(256)
gumbel_softmax_kernel(const float* __restrict__ logits,
                      const float* __restrict__ u,
                      float* __restrict__ out)
{
    const int warp = threadIdx.x >> 5;
    const int lane = threadIdx.x & 31;
    const int row = blockIdx.x * 8 + warp;

    const float* lr = logits + (size_t)row * LG_PITCH;
    const float* ur = u + (size_t)row * O_DIM;
    float* orow = out + (size_t)row * O_DIM;

    const int offs[13] = {0, 29, 31, 32, 38, 45, 104, 105, 129, 205, 916, 919, 928};
    const int nums[13] = {29, 2, 1, 6, 7, 59, 1, 24, 76, 711, 3, 9, 1};
    const float invT = 1.0f / 0.8f;
    const float EPS = 1e-20f;

    for (int s = 0; s < 13; s++) {
        const int o = offs[s];
        const int n = nums[s];
        if (n == 1) {
            if (lane == 0) orow[o] = lr[o];
            continue;
        }
        float yv[23];
        float mx = -1e30f;
        #pragma unroll
        for (int it = 0; it < 23; it++) {
            const int i = lane + it * 32;
            float y = -1e30f;
            if (i < n) {
                const float g = -__logf(-__logf(ur[o + i] + EPS) + EPS);
                y = (lr[o + i] + g) * invT;
            }
            yv[it] = y;
            mx = fmaxf(mx, y);
        }
        #pragma unroll
        for (int d = 16; d; d >>= 1) mx = fmaxf(mx, __shfl_xor_sync(0xFFFFFFFFu, mx, d));

        float sum = 0.0f;
        #pragma unroll
        for (int it = 0; it < 23; it++) {
            const int i = lane + it * 32;
            float e = 0.0f;
            if (i < n) e = __expf(yv[it] - mx);
            yv[it] = e;
            sum += e;
        }
        #pragma unroll
        for (int d = 16; d; d >>= 1) sum += __shfl_xor_sync(0xFFFFFFFFu, sum, d);
        const float inv = 1.0f / sum;

        #pragma unroll
        for (int it = 0; it < 23; it++) {
            const int i = lane + it * 32;
            if (i < n) orow[o + i] = yv[it] * inv;
        }
    }
}

// ---------------------------------------------------------------------------
// kernel_launch: prep, then per layer launch BOTH gemm variants (exactly one
// has a compiled body for the loaded cubin; the other is an empty kernel).
// ---------------------------------------------------------------------------
extern "C" void kernel_launch(void* const* d_in, const int* in_sizes, int n_in,
                              void* d_out, int out_size)
{
    const float* x  = (const float*)d_in[0];
    const float* W1 = (const float*)d_in[1];
    const float* b1 = (const float*)d_in[2];
    const float* W2 = (const float*)d_in[3];
    const float* b2 = (const float*)d_in[4];
    const float* W3 = (const float*)d_in[5];
    const float* b3 = (const float*)d_in[6];
    const float* u  = (const float*)d_in[7];
    float* out = (float*)d_out;

    __nv_bfloat16 *xhi, *xlo, *a1hi, *a1lo, *a2hi, *a2lo;
    __nv_bfloat16 *w1hi, *w1lo, *w2hi, *w2lo, *w3hi, *w3lo;
    float* lgp;
    cudaGetSymbolAddress((void**)&xhi, g_xhi);
    cudaGetSymbolAddress((void**)&xlo, g_xlo);
    cudaGetSymbolAddress((void**)&a1hi, g_a1hi);
    cudaGetSymbolAddress((void**)&a1lo, g_a1lo);
    cudaGetSymbolAddress((void**)&a2hi, g_a2hi);
    cudaGetSymbolAddress((void**)&a2lo, g_a2lo);
    cudaGetSymbolAddress((void**)&lgp, g_logits);
    cudaGetSymbolAddress((void**)&w1hi, g_w1hi);
    cudaGetSymbolAddress((void**)&w1lo, g_w1lo);
    cudaGetSymbolAddress((void**)&w2hi, g_w2hi);
    cudaGetSymbolAddress((void**)&w2lo, g_w2lo);
    cudaGetSymbolAddress((void**)&w3hi, g_w3hi);
    cudaGetSymbolAddress((void**)&w3lo, g_w3lo);

    cudaFuncSetAttribute(gemm_tc,  cudaFuncAttributeMaxDynamicSharedMemorySize, SMEM_BYTES);
    cudaFuncSetAttribute(gemm_mma, cudaFuncAttributeMaxDynamicSharedMemorySize, MM_SMEM);

    split_x_kernel<<<(M_DIM * D_DIM) / 256, 256>>>(x, xhi, xlo, M_DIM * D_DIM);
    wsplit_kernel<<<(H_DIM * D_DIM) / 256, 256>>>(W1, w1hi, w1lo, D_DIM, H_DIM, H_DIM);
    wsplit_kernel<<<(H_DIM * H_DIM) / 256, 256>>>(W2, w2hi, w2lo, H_DIM, H_DIM, H_DIM);
    wsplit_kernel<<<(H_DIM * H_DIM) / 256, 256>>>(W3, w3hi, w3lo, H_DIM, O_DIM, H_DIM);

    dim3 gridTC(H_DIM / 256, M_DIM / 256);   // (4, 128)
    dim3 gridMM(H_DIM / 128, M_DIM / 128);   // (8, 256)

    // L1: h1 = elu(x @ W1 + b1)
    gemm_tc <<<gridTC, 256, SMEM_BYTES>>>(xhi, xlo, w1hi, w1lo, b1, D_DIM, 0, nullptr, a1hi, a1lo);
    gemm_mma<<<gridMM, 256, MM_SMEM>>>(xhi, xlo, w1hi, w1lo, b1, D_DIM, 0, nullptr, a1hi, a1lo);
    // L2: h2 = sigmoid(h1 @ W2 + b2)
    gemm_tc <<<gridTC, 256, SMEM_BYTES>>>(a1hi, a1lo, w2hi, w2lo, b2, H_DIM, 1, nullptr, a2hi, a2lo);
    gemm_mma<<<gridMM, 256, MM_SMEM>>>(a1hi, a1lo, w2hi, w2lo, b2, H_DIM, 1, nullptr, a2hi, a2lo);
    // L3: logits = h2 @ W3 + b3 (cols < 929, pitch 1024)
    gemm_tc <<<gridTC, 256, SMEM_BYTES>>>(a2hi, a2lo, w3hi, w3lo, b3, H_DIM, 2, lgp, nullptr, nullptr);
    gemm_mma<<<gridMM, 256, MM_SMEM>>>(a2hi, a2lo, w3hi, w3lo, b3, H_DIM, 2, lgp, nullptr, nullptr);
    // Gumbel softmax
    gumbel_softmax_kernel<<<M_DIM / 8, 256>>>(lgp, u, out);
}